// round 7
// baseline (speedup 1.0000x reference)
#include <cuda_runtime.h>
#include <cuda_fp16.h>
#include <cstdint>

#define DIM_ 4096
#define BM 128
#define BN 128
#define BKH 32               // fp16 k per chunk (64B per row)
#define NCH (DIM_ / BKH)     // 128 chunks
#define ROWB 80              // padded smem row stride (64B data + 16B pad), ldsm conflict-free
#define TILEB (BM * ROWB)    // 10240 B per tile
#define STGB (4 * TILEB)     // 4 tiles per stage (A0,A1,B0,B1)
#define NSTG 4

// ---------------- scratch (allocation-free rule: __device__ globals) --------
__device__ unsigned short g_x0[(size_t)DIM_ * DIM_];   // x splits (scale 1)
__device__ unsigned short g_x1[(size_t)DIM_ * DIM_];
__device__ unsigned short g_p0[(size_t)DIM_ * DIM_];   // 64*Pi splits (K-major rows)
__device__ unsigned short g_p1[(size_t)DIM_ * DIM_];
__device__ unsigned short g_t0[(size_t)DIM_ * DIM_];   // 64*Pi^T splits (K-major rows)
__device__ unsigned short g_t1[(size_t)DIM_ * DIM_];
__device__ unsigned short g_y0[(size_t)DIM_ * DIM_];   // 64*y~ split hi
__device__ unsigned short g_y1[(size_t)DIM_ * DIM_];   // 64*y~ split lo

// ---------------- PTX helpers (all legal at compute_103) --------------------
__device__ __forceinline__ uint32_t smem_u32(const void* p) {
    uint32_t a;
    asm("{ .reg .u64 t; cvta.to.shared.u64 t, %1; cvt.u32.u64 %0, t; }" : "=r"(a) : "l"(p));
    return a;
}
__device__ __forceinline__ void cpasync16(uint32_t sa, const void* g) {
    asm volatile("cp.async.cg.shared.global [%0], [%1], 16;" :: "r"(sa), "l"(g));
}
__device__ __forceinline__ void ldsm4(uint32_t* r, uint32_t a) {
    asm volatile("ldmatrix.sync.aligned.m8n8.x4.shared.b16 {%0,%1,%2,%3}, [%4];"
                 : "=r"(r[0]), "=r"(r[1]), "=r"(r[2]), "=r"(r[3]) : "r"(a));
}
__device__ __forceinline__ void mma16816(float* d, const uint32_t* a, const uint32_t* b) {
    asm volatile("mma.sync.aligned.m16n8k16.row.col.f32.f16.f16.f32 "
                 "{%0,%1,%2,%3}, {%4,%5,%6,%7}, {%8,%9}, {%0,%1,%2,%3};"
                 : "+f"(d[0]), "+f"(d[1]), "+f"(d[2]), "+f"(d[3])
                 : "r"(a[0]), "r"(a[1]), "r"(a[2]), "r"(a[3]), "r"(b[0]), "r"(b[1]));
}
#define CP_COMMIT() asm volatile("cp.async.commit_group;" ::: "memory")
#define CP_WAIT2()  asm volatile("cp.async.wait_group 2;" ::: "memory")

// ---------------- fp16 2-split (Markidis) -----------------------------------
__device__ __forceinline__ void hsplit2(float v, unsigned short& b0, unsigned short& b1) {
    __half h0 = __float2half_rn(v);
    float r = v - __half2float(h0);
    __half h1 = __float2half_rn(r);
    b0 = *reinterpret_cast<unsigned short*>(&h0);
    b1 = *reinterpret_cast<unsigned short*>(&h1);
}

template<int SCALE>
__global__ void split2_kernel(const float4* __restrict__ in,
                              uint32_t* __restrict__ o0, uint32_t* __restrict__ o1) {
    int i = blockIdx.x * blockDim.x + threadIdx.x;   // one float4 per thread
    float4 v = in[i];
    unsigned short a0[4], a1[4];
    hsplit2(v.x * SCALE, a0[0], a1[0]);
    hsplit2(v.y * SCALE, a0[1], a1[1]);
    hsplit2(v.z * SCALE, a0[2], a1[2]);
    hsplit2(v.w * SCALE, a0[3], a1[3]);
    o0[2 * i] = a0[0] | ((uint32_t)a0[1] << 16); o0[2 * i + 1] = a0[2] | ((uint32_t)a0[3] << 16);
    o1[2 * i] = a1[0] | ((uint32_t)a1[1] << 16); o1[2 * i + 1] = a1[2] | ((uint32_t)a1[3] << 16);
}

__global__ void transsplit2_kernel(const float* __restrict__ Pi,
                                   unsigned short* __restrict__ t0,
                                   unsigned short* __restrict__ t1) {
    __shared__ float tile[32][33];
    int tx = threadIdx.x, ty = threadIdx.y;
    int c0 = blockIdx.x * 32, r0 = blockIdx.y * 32;
    #pragma unroll
    for (int i = 0; i < 4; ++i)
        tile[ty + 8 * i][tx] = Pi[(size_t)(r0 + ty + 8 * i) * DIM_ + c0 + tx];
    __syncthreads();
    #pragma unroll
    for (int i = 0; i < 4; ++i) {
        float v = tile[tx][ty + 8 * i] * 64.0f;
        unsigned short b0, b1;
        hsplit2(v, b0, b1);
        size_t o = (size_t)(c0 + ty + 8 * i) * DIM_ + r0 + tx;
        t0[o] = b0;
        t1[o] = b1;
    }
}

// ---------------- split GEMM via mma.sync (HMMA fp16) -----------------------
// NPROD=4: a0b0 + a0b1 + a1b0 + a1b1 ; NPROD=3 drops a1b1.
// All operands K-major. QUANT: acc holds 64*y; quantize against 64*bnd, emit
// fp16 split pair of 64*codebook. !QUANT: acc holds 4096*x~, scale by 1/4096.
template<int NPROD, bool QUANT>
__global__ __launch_bounds__(512, 1)
void hmma_gemm(const unsigned short* __restrict__ A0, const unsigned short* __restrict__ A1,
               const unsigned short* __restrict__ Bm0, const unsigned short* __restrict__ Bm1,
               const float* __restrict__ cb, float* __restrict__ Cout,
               unsigned short* __restrict__ Y0, unsigned short* __restrict__ Y1)
{
    extern __shared__ char smem[];
    const uint32_t sb = smem_u32(smem);
    __shared__ float s_bnd[15];        // 64 * midpoints
    __shared__ uint32_t s_cbp[16];     // packed fp16 split of 64*codebook

    const int tid = threadIdx.x;
    const int w = tid >> 5, l = tid & 31;
    const int wm = w & 3, wn = w >> 2;          // 4x4 warp grid, warp tile 32x32
    const int row0 = blockIdx.y * BM;
    const int col0 = blockIdx.x * BN;

    if (QUANT) {
        if (tid < 16) {
            float c = cb[tid] * 64.0f;
            unsigned short b0, b1;
            hsplit2(c, b0, b1);
            s_cbp[tid] = (uint32_t)b0 | ((uint32_t)b1 << 16);
        }
        if (tid < 15) s_bnd[tid] = 32.0f * (cb[tid] + cb[tid + 1]);   // 64 * midpoint
        // visibility: first main-loop __syncthreads
    }

    const unsigned short* srcs[4] = {A0, A1, Bm0, Bm1};
    const int rb[4] = {row0, row0, col0, col0};

    // one 16B cp.async per thread per tile: r = tid/4, c = tid%4
    const int cr = tid >> 2, cc = tid & 3;
    const unsigned short* gp[4];
    #pragma unroll
    for (int t = 0; t < 4; ++t)
        gp[t] = srcs[t] + (size_t)(rb[t] + cr) * DIM_ + cc * 8;
    const uint32_t swr = cr * ROWB + cc * 16;

    auto load_chunk = [&](int ch, int st) {
        const int k0 = ch * BKH;
        const uint32_t stg = sb + st * STGB;
        #pragma unroll
        for (int t = 0; t < 4; ++t)
            cpasync16(stg + t * TILEB + swr, gp[t] + k0);
        CP_COMMIT();
    };

    float acc[2][4][4];
    #pragma unroll
    for (int f = 0; f < 2; ++f)
        #pragma unroll
        for (int j = 0; j < 4; ++j)
            #pragma unroll
            for (int q = 0; q < 4; ++q) acc[f][j][q] = 0.0f;

    // lane-invariant fragment offsets (bytes within a tile)
    const uint32_t a_off = (uint32_t)(wm * 32 + (l & 15)) * ROWB + (l >> 4) * 16;
    const uint32_t b_off = (uint32_t)(wn * 32 + (l & 7) + ((l >> 4) & 1) * 8) * ROWB
                         + ((l >> 3) & 1) * 16;

    load_chunk(0, 0);
    load_chunk(1, 1);
    load_chunk(2, 2);

    for (int t = 0; t < NCH; ++t) {
        const int st = t & 3;
        CP_WAIT2();                      // with uniform commits: chunk t arrived
        __syncthreads();
        if (t + 3 < NCH) load_chunk(t + 3, (t + 3) & 3);
        else             CP_COMMIT();    // empty group keeps pending-count math exact

        const uint32_t base = sb + st * STGB;
        #pragma unroll
        for (int ks = 0; ks < 2; ++ks) {
            uint32_t afr[2][2][4];              // [split][mfrag][4]
            #pragma unroll
            for (int s = 0; s < 2; ++s)
                #pragma unroll
                for (int f = 0; f < 2; ++f)
                    ldsm4(afr[s][f], base + s * TILEB + a_off + f * 16 * ROWB + ks * 32);

            #pragma unroll
            for (int sB = 0; sB < 2; ++sB) {
                uint32_t bfr[2][4];             // 4 n8-frags of k16
                #pragma unroll
                for (int p = 0; p < 2; ++p)
                    ldsm4(bfr[p], base + (2 + sB) * TILEB + b_off + p * 16 * ROWB + ks * 32);
                #pragma unroll
                for (int f = 0; f < 2; ++f)
                    #pragma unroll
                    for (int j = 0; j < 4; ++j)
                        mma16816(acc[f][j], afr[0][f], &bfr[j >> 1][(j & 1) * 2]);
                if (sB == 0 || NPROD == 4) {
                    #pragma unroll
                    for (int f = 0; f < 2; ++f)
                        #pragma unroll
                        for (int j = 0; j < 4; ++j)
                            mma16816(acc[f][j], afr[1][f], &bfr[j >> 1][(j & 1) * 2]);
                }
            }
        }
    }

    // ---- register epilogue --------------------------------------------------
    // acc[f][j][q]: m = wm*32 + f*16 + (q>=2)*8 + l/4 ; n = wn*32 + j*8 + 2*(l&3) + (q&1)
    #pragma unroll
    for (int f = 0; f < 2; ++f) {
        #pragma unroll
        for (int j = 0; j < 4; ++j) {
            const int nb = col0 + wn * 32 + j * 8 + (l & 3) * 2;
            #pragma unroll
            for (int h = 0; h < 2; ++h) {
                const int row = row0 + wm * 32 + f * 16 + h * 8 + (l >> 2);
                const float va = acc[f][j][2 * h];
                const float vb = acc[f][j][2 * h + 1];
                if (QUANT) {
                    int ia = 0, ib = 0;
                    #pragma unroll
                    for (int q = 0; q < 15; ++q) {
                        ia += (va > s_bnd[q]) ? 1 : 0;
                        ib += (vb > s_bnd[q]) ? 1 : 0;
                    }
                    const uint32_t qa = s_cbp[ia], qb = s_cbp[ib];
                    const size_t o = ((size_t)row * DIM_ + nb) >> 1;   // u32 index
                    ((uint32_t*)Y0)[o] = (qa & 0xFFFFu) | (qb << 16);
                    ((uint32_t*)Y1)[o] = (qa >> 16) | (qb & 0xFFFF0000u);
                } else {
                    *(float2*)(Cout + (size_t)row * DIM_ + nb) =
                        make_float2(va * (1.0f / 4096.0f), vb * (1.0f / 4096.0f));
                }
            }
        }
    }
}

// ---------------- host ------------------------------------------------------
extern "C" void kernel_launch(void* const* d_in, const int* in_sizes, int n_in,
                              void* d_out, int out_size)
{
    const float* x  = (const float*)d_in[0];
    const float* Pi = (const float*)d_in[1];
    const float* cb = (const float*)d_in[2];
    float* out = (float*)d_out;

    unsigned short *x0, *x1, *p0, *p1, *t0, *t1, *y0, *y1;
    cudaGetSymbolAddress((void**)&x0, g_x0);
    cudaGetSymbolAddress((void**)&x1, g_x1);
    cudaGetSymbolAddress((void**)&p0, g_p0);
    cudaGetSymbolAddress((void**)&p1, g_p1);
    cudaGetSymbolAddress((void**)&t0, g_t0);
    cudaGetSymbolAddress((void**)&t1, g_t1);
    cudaGetSymbolAddress((void**)&y0, g_y0);
    cudaGetSymbolAddress((void**)&y1, g_y1);

    const size_t N = (size_t)DIM_ * DIM_;
    const int smem = NSTG * STGB;   // 163840 B
    cudaFuncSetAttribute(hmma_gemm<4, true>,
                         cudaFuncAttributeMaxDynamicSharedMemorySize, smem);
    cudaFuncSetAttribute(hmma_gemm<3, false>,
                         cudaFuncAttributeMaxDynamicSharedMemorySize, smem);

    // 1) splits: x -> (x0,x1) scale 1 ; 64*Pi -> (p0,p1) ; 64*Pi^T -> (t0,t1)
    split2_kernel<1><<<(int)(N / 4 / 256), 256>>>((const float4*)x, (uint32_t*)x0, (uint32_t*)x1);
    split2_kernel<64><<<(int)(N / 4 / 256), 256>>>((const float4*)Pi, (uint32_t*)p0, (uint32_t*)p1);
    transsplit2_kernel<<<dim3(DIM_ / 32, DIM_ / 32), dim3(32, 8)>>>(Pi, t0, t1);

    dim3 grid(DIM_ / BN, DIM_ / BM);
    // 2) GEMM1 + quantize (4 products): (y0,y1) = split(64*Q(x @ Pi^T))
    hmma_gemm<4, true><<<grid, 512, smem>>>(x0, x1, p0, p1, cb, nullptr, y0, y1);
    // 3) GEMM2 (3 products): out = (64y~ @ 64Pi) / 4096
    hmma_gemm<3, false><<<grid, 512, smem>>>(y0, y1, t0, t1, nullptr, out, nullptr, nullptr);
}

// round 8
// speedup vs baseline: 1.1012x; 1.1012x over previous
#include <cuda_runtime.h>
#include <cuda_fp16.h>
#include <cstdint>

#define DIM_ 4096
#define BM 128
#define BN 128
#define BKH 32               // fp16 k per chunk (64B per row)
#define NCH (DIM_ / BKH)     // 128 chunks
#define ROWB 80              // padded smem row stride (64B data + 16B pad), ldsm conflict-free
#define TILEB (BM * ROWB)    // 10240 B per tile
#define STGB (4 * TILEB)     // 4 tiles per stage (A0,A1,B0,B1)
#define NSTG 4

// Scale scheme (all powers of 2 -> exact):
//   x  * 2^12 -> (x0,x1)    residuals ~ +-2      (fp16-normal)
//   Pi * 2^16 -> (p0,p1)    residuals ~ +-0.5    (fp16-normal)
//   Pi^T*2^16 -> (t0,t1)
//   y~ stored as split of c*2^12
//   GEMM acc = 2^28 * (y or x~); boundaries *2^27; output *2^-28.

// ---------------- scratch (allocation-free rule: __device__ globals) --------
__device__ unsigned short g_x0[(size_t)DIM_ * DIM_];
__device__ unsigned short g_x1[(size_t)DIM_ * DIM_];
__device__ unsigned short g_p0[(size_t)DIM_ * DIM_];
__device__ unsigned short g_p1[(size_t)DIM_ * DIM_];
__device__ unsigned short g_t0[(size_t)DIM_ * DIM_];
__device__ unsigned short g_t1[(size_t)DIM_ * DIM_];
__device__ unsigned short g_y0[(size_t)DIM_ * DIM_];
__device__ unsigned short g_y1[(size_t)DIM_ * DIM_];

// ---------------- PTX helpers (all legal at compute_103) --------------------
__device__ __forceinline__ uint32_t smem_u32(const void* p) {
    uint32_t a;
    asm("{ .reg .u64 t; cvta.to.shared.u64 t, %1; cvt.u32.u64 %0, t; }" : "=r"(a) : "l"(p));
    return a;
}
__device__ __forceinline__ void cpasync16(uint32_t sa, const void* g) {
    asm volatile("cp.async.cg.shared.global [%0], [%1], 16;" :: "r"(sa), "l"(g));
}
__device__ __forceinline__ void ldsm4(uint32_t* r, uint32_t a) {
    asm volatile("ldmatrix.sync.aligned.m8n8.x4.shared.b16 {%0,%1,%2,%3}, [%4];"
                 : "=r"(r[0]), "=r"(r[1]), "=r"(r[2]), "=r"(r[3]) : "r"(a));
}
__device__ __forceinline__ void mma16816(float* d, const uint32_t* a, const uint32_t* b) {
    asm volatile("mma.sync.aligned.m16n8k16.row.col.f32.f16.f16.f32 "
                 "{%0,%1,%2,%3}, {%4,%5,%6,%7}, {%8,%9}, {%0,%1,%2,%3};"
                 : "+f"(d[0]), "+f"(d[1]), "+f"(d[2]), "+f"(d[3])
                 : "r"(a[0]), "r"(a[1]), "r"(a[2]), "r"(a[3]), "r"(b[0]), "r"(b[1]));
}
#define CP_COMMIT() asm volatile("cp.async.commit_group;" ::: "memory")
#define CP_WAIT2()  asm volatile("cp.async.wait_group 2;" ::: "memory")

// ---------------- fp16 2-split (Markidis, pre-scaled) -----------------------
__device__ __forceinline__ void hsplit2(float v, unsigned short& b0, unsigned short& b1) {
    __half h0 = __float2half_rn(v);
    float r = v - __half2float(h0);
    __half h1 = __float2half_rn(r);
    b0 = *reinterpret_cast<unsigned short*>(&h0);
    b1 = *reinterpret_cast<unsigned short*>(&h1);
}

template<int SCALE>
__global__ void split2_kernel(const float4* __restrict__ in,
                              uint32_t* __restrict__ o0, uint32_t* __restrict__ o1) {
    int i = blockIdx.x * blockDim.x + threadIdx.x;   // one float4 per thread
    float4 v = in[i];
    const float s = (float)SCALE;
    unsigned short a0[4], a1[4];
    hsplit2(v.x * s, a0[0], a1[0]);
    hsplit2(v.y * s, a0[1], a1[1]);
    hsplit2(v.z * s, a0[2], a1[2]);
    hsplit2(v.w * s, a0[3], a1[3]);
    o0[2 * i] = a0[0] | ((uint32_t)a0[1] << 16); o0[2 * i + 1] = a0[2] | ((uint32_t)a0[3] << 16);
    o1[2 * i] = a1[0] | ((uint32_t)a1[1] << 16); o1[2 * i + 1] = a1[2] | ((uint32_t)a1[3] << 16);
}

__global__ void transsplit2_kernel(const float* __restrict__ Pi,
                                   unsigned short* __restrict__ t0,
                                   unsigned short* __restrict__ t1) {
    __shared__ float tile[32][33];
    int tx = threadIdx.x, ty = threadIdx.y;
    int c0 = blockIdx.x * 32, r0 = blockIdx.y * 32;
    #pragma unroll
    for (int i = 0; i < 4; ++i)
        tile[ty + 8 * i][tx] = Pi[(size_t)(r0 + ty + 8 * i) * DIM_ + c0 + tx];
    __syncthreads();
    #pragma unroll
    for (int i = 0; i < 4; ++i) {
        float v = tile[tx][ty + 8 * i] * 65536.0f;
        unsigned short b0, b1;
        hsplit2(v, b0, b1);
        size_t o = (size_t)(c0 + ty + 8 * i) * DIM_ + r0 + tx;
        t0[o] = b0;
        t1[o] = b1;
    }
}

// ---------------- split GEMM via mma.sync (HMMA fp16) -----------------------
// 3 products: a0b0 + a0b1 + a1b0 (a1b1 ~ 2^-22, below fp32 accum noise).
// All operands K-major. QUANT: acc = 2^28*y; compare vs 2^27*(c_i+c_{i+1});
// emit fp16 split pair of 2^12*codebook. !QUANT: acc = 2^28*x~, scale 2^-28.
template<bool QUANT>
__global__ __launch_bounds__(512, 1)
void hmma_gemm(const unsigned short* __restrict__ A0, const unsigned short* __restrict__ A1,
               const unsigned short* __restrict__ Bm0, const unsigned short* __restrict__ Bm1,
               const float* __restrict__ cb, float* __restrict__ Cout,
               unsigned short* __restrict__ Y0, unsigned short* __restrict__ Y1)
{
    extern __shared__ char smem[];
    const uint32_t sb = smem_u32(smem);
    __shared__ float s_bnd[15];        // 2^27 * (c_i + c_{i+1})
    __shared__ uint32_t s_cbp[16];     // packed fp16 split of 2^12 * codebook

    const int tid = threadIdx.x;
    const int w = tid >> 5, l = tid & 31;
    const int wm = w & 3, wn = w >> 2;          // 4x4 warp grid, warp tile 32x32
    const int row0 = blockIdx.y * BM;
    const int col0 = blockIdx.x * BN;

    if (QUANT) {
        if (tid < 16) {
            float c = cb[tid] * 4096.0f;
            unsigned short b0, b1;
            hsplit2(c, b0, b1);
            s_cbp[tid] = (uint32_t)b0 | ((uint32_t)b1 << 16);
        }
        if (tid < 15) s_bnd[tid] = (cb[tid] + cb[tid + 1]) * 134217728.0f;  // 2^27
        // visibility: first main-loop __syncthreads
    }

    const unsigned short* srcs[4] = {A0, A1, Bm0, Bm1};
    const int rb[4] = {row0, row0, col0, col0};

    // one 16B cp.async per thread per tile: r = tid/4, c = tid%4
    const int cr = tid >> 2, cc = tid & 3;
    const unsigned short* gp[4];
    #pragma unroll
    for (int t = 0; t < 4; ++t)
        gp[t] = srcs[t] + (size_t)(rb[t] + cr) * DIM_ + cc * 8;
    const uint32_t swr = cr * ROWB + cc * 16;

    auto load_chunk = [&](int ch, int st) {
        const int k0 = ch * BKH;
        const uint32_t stg = sb + st * STGB;
        #pragma unroll
        for (int t = 0; t < 4; ++t)
            cpasync16(stg + t * TILEB + swr, gp[t] + k0);
        CP_COMMIT();
    };

    float acc[2][4][4];
    #pragma unroll
    for (int f = 0; f < 2; ++f)
        #pragma unroll
        for (int j = 0; j < 4; ++j)
            #pragma unroll
            for (int q = 0; q < 4; ++q) acc[f][j][q] = 0.0f;

    // lane-invariant fragment offsets (bytes within a tile)
    const uint32_t a_off = (uint32_t)(wm * 32 + (l & 15)) * ROWB + (l >> 4) * 16;
    const uint32_t b_off = (uint32_t)(wn * 32 + (l & 7) + ((l >> 4) & 1) * 8) * ROWB
                         + ((l >> 3) & 1) * 16;

    load_chunk(0, 0);
    load_chunk(1, 1);
    load_chunk(2, 2);

    for (int t = 0; t < NCH; ++t) {
        const int st = t & 3;
        CP_WAIT2();                      // with uniform commits: chunk t arrived
        __syncthreads();
        if (t + 3 < NCH) load_chunk(t + 3, (t + 3) & 3);
        else             CP_COMMIT();    // empty group keeps pending-count math exact

        const uint32_t base = sb + st * STGB;
        #pragma unroll
        for (int ks = 0; ks < 2; ++ks) {
            uint32_t afr[2][2][4];              // [split][mfrag][4]
            #pragma unroll
            for (int s = 0; s < 2; ++s)
                #pragma unroll
                for (int f = 0; f < 2; ++f)
                    ldsm4(afr[s][f], base + s * TILEB + a_off + f * 16 * ROWB + ks * 32);

            #pragma unroll
            for (int sB = 0; sB < 2; ++sB) {
                uint32_t bfr[2][4];             // 4 n8-frags of k16
                #pragma unroll
                for (int p = 0; p < 2; ++p)
                    ldsm4(bfr[p], base + (2 + sB) * TILEB + b_off + p * 16 * ROWB + ks * 32);
                // sB==0: a0*b0 + a1*b0 ; sB==1: a0*b1
                #pragma unroll
                for (int f = 0; f < 2; ++f)
                    #pragma unroll
                    for (int j = 0; j < 4; ++j)
                        mma16816(acc[f][j], afr[0][f], &bfr[j >> 1][(j & 1) * 2]);
                if (sB == 0) {
                    #pragma unroll
                    for (int f = 0; f < 2; ++f)
                        #pragma unroll
                        for (int j = 0; j < 4; ++j)
                            mma16816(acc[f][j], afr[1][f], &bfr[j >> 1][(j & 1) * 2]);
                }
            }
        }
    }

    // ---- register epilogue --------------------------------------------------
    // acc[f][j][q]: m = wm*32 + f*16 + (q>=2)*8 + l/4 ; n = wn*32 + j*8 + 2*(l&3) + (q&1)
    #pragma unroll
    for (int f = 0; f < 2; ++f) {
        #pragma unroll
        for (int j = 0; j < 4; ++j) {
            const int nb = col0 + wn * 32 + j * 8 + (l & 3) * 2;
            #pragma unroll
            for (int h = 0; h < 2; ++h) {
                const int row = row0 + wm * 32 + f * 16 + h * 8 + (l >> 2);
                const float va = acc[f][j][2 * h];
                const float vb = acc[f][j][2 * h + 1];
                if (QUANT) {
                    int ia = 0, ib = 0;
                    #pragma unroll
                    for (int q = 0; q < 15; ++q) {
                        ia += (va > s_bnd[q]) ? 1 : 0;
                        ib += (vb > s_bnd[q]) ? 1 : 0;
                    }
                    const uint32_t qa = s_cbp[ia], qb = s_cbp[ib];
                    const size_t o = ((size_t)row * DIM_ + nb) >> 1;   // u32 index
                    ((uint32_t*)Y0)[o] = (qa & 0xFFFFu) | (qb << 16);
                    ((uint32_t*)Y1)[o] = (qa >> 16) | (qb & 0xFFFF0000u);
                } else {
                    const float s = 1.0f / 268435456.0f;   // 2^-28
                    *(float2*)(Cout + (size_t)row * DIM_ + nb) =
                        make_float2(va * s, vb * s);
                }
            }
        }
    }
}

// ---------------- host ------------------------------------------------------
extern "C" void kernel_launch(void* const* d_in, const int* in_sizes, int n_in,
                              void* d_out, int out_size)
{
    const float* x  = (const float*)d_in[0];
    const float* Pi = (const float*)d_in[1];
    const float* cb = (const float*)d_in[2];
    float* out = (float*)d_out;

    unsigned short *x0, *x1, *p0, *p1, *t0, *t1, *y0, *y1;
    cudaGetSymbolAddress((void**)&x0, g_x0);
    cudaGetSymbolAddress((void**)&x1, g_x1);
    cudaGetSymbolAddress((void**)&p0, g_p0);
    cudaGetSymbolAddress((void**)&p1, g_p1);
    cudaGetSymbolAddress((void**)&t0, g_t0);
    cudaGetSymbolAddress((void**)&t1, g_t1);
    cudaGetSymbolAddress((void**)&y0, g_y0);
    cudaGetSymbolAddress((void**)&y1, g_y1);

    const size_t N = (size_t)DIM_ * DIM_;
    const int smem = NSTG * STGB;   // 163840 B
    cudaFuncSetAttribute(hmma_gemm<true>,
                         cudaFuncAttributeMaxDynamicSharedMemorySize, smem);
    cudaFuncSetAttribute(hmma_gemm<false>,
                         cudaFuncAttributeMaxDynamicSharedMemorySize, smem);

    // 1) splits: 2^12*x -> (x0,x1) ; 2^16*Pi -> (p0,p1) ; 2^16*Pi^T -> (t0,t1)
    split2_kernel<4096><<<(int)(N / 4 / 256), 256>>>((const float4*)x,
                                                     (uint32_t*)x0, (uint32_t*)x1);
    split2_kernel<65536><<<(int)(N / 4 / 256), 256>>>((const float4*)Pi,
                                                      (uint32_t*)p0, (uint32_t*)p1);
    transsplit2_kernel<<<dim3(DIM_ / 32, DIM_ / 32), dim3(32, 8)>>>(Pi, t0, t1);

    dim3 grid(DIM_ / BN, DIM_ / BM);
    // 2) GEMM1 + quantize: (y0,y1) = split(2^12 * Q((2^28 y)/2^28))
    hmma_gemm<true><<<grid, 512, smem>>>(x0, x1, p0, p1, cb, nullptr, y0, y1);
    // 3) GEMM2: out = (2^12 y~ @ 2^16 Pi) * 2^-28
    hmma_gemm<false><<<grid, 512, smem>>>(y0, y1, t0, t1, nullptr, out, nullptr, nullptr);
}